// round 16
// baseline (speedup 1.0000x reference)
#include <cuda_runtime.h>
#include <cuda_bf16.h>
#include <math.h>
#include <stdint.h>

#define BATCH 8
#define CH    256
#define NQ    2048
#define MPTS  4096
#define KNN   10

typedef unsigned short u16;

static __device__ u16   g_xTh [(size_t)BATCH * NQ * CH];
static __device__ u16   g_xTl [(size_t)BATCH * NQ * CH];
static __device__ u16   g_Wqkh[CH * CH], g_Wqkl[CH * CH];
static __device__ u16   g_Wvh [CH * CH], g_Wvl [CH * CH];
static __device__ u16   g_Wth [CH * CH], g_Wtl [CH * CH];
static __device__ u16   g_Yqkth[(size_t)BATCH * NQ * CH];
static __device__ u16   g_Yqktl[(size_t)BATCH * NQ * CH];
static __device__ float g_Yv  [(size_t)BATCH * CH * NQ];
static __device__ float g_energy[(size_t)BATCH * NQ * NQ];
static __device__ float g_pm  [(size_t)BATCH * 16 * NQ];
static __device__ float g_ps  [(size_t)BATCH * 16 * NQ];
static __device__ float g_rmax[BATCH * NQ];
static __device__ float g_rinv[BATCH * NQ];
static __device__ u16   g_dbufTh[(size_t)BATCH * NQ * CH];
static __device__ u16   g_dbufTl[(size_t)BATCH * NQ * CH];
static __device__ float g_query[(size_t)BATCH * 3 * NQ];

__device__ __forceinline__ uint32_t smem_u32(const void* p) {
    uint32_t a;
    asm("{ .reg .u64 t; cvta.to.shared.u64 t, %1; cvt.u32.u64 %0, t; }" : "=r"(a) : "l"(p));
    return a;
}
__device__ __forceinline__ uint32_t f2tf32(float f) {
    uint32_t r;
    asm("cvt.rna.tf32.f32 %0, %1;" : "=r"(r) : "f"(f));
    return r;
}
__device__ __forceinline__ void bf16split(float v, u16& h, u16& l) {
    __nv_bfloat16 hb = __float2bfloat16_rn(v);
    h = __bfloat16_as_ushort(hb);
    __nv_bfloat16 lb = __float2bfloat16_rn(v - __bfloat162float(hb));
    l = __bfloat16_as_ushort(lb);
}
__device__ __forceinline__ float bfpair(uint32_t hw, uint32_t lw, int sel) {
    u16 h = (u16)(sel ? (hw >> 16) : (hw & 0xffff));
    u16 l = (u16)(sel ? (lw >> 16) : (lw & 0xffff));
    return __bfloat162float(__ushort_as_bfloat16(h)) +
           __bfloat162float(__ushort_as_bfloat16(l));
}
__device__ __forceinline__ void cp16(uint32_t dst, const void* src) {
    asm volatile("cp.async.ca.shared.global [%0], [%1], 16;" :: "r"(dst), "l"(src) : "memory");
}
#define CP_COMMIT() asm volatile("cp.async.commit_group;" ::: "memory")
#define CP_WAIT1()  asm volatile("cp.async.wait_group 1;" ::: "memory")
#define CP_WAIT0()  asm volatile("cp.async.wait_group 0;" ::: "memory")
#define LDSM_X4(r0, r1, r2, r3, addr) \
    asm volatile("ldmatrix.sync.aligned.m8n8.x4.shared.b16 {%0,%1,%2,%3}, [%4];" \
        : "=r"(r0), "=r"(r1), "=r"(r2), "=r"(r3) : "r"(addr))
#define MMAT(d, a, bb) \
    asm volatile("mma.sync.aligned.m16n8k8.row.col.f32.tf32.tf32.f32 " \
        "{%0,%1,%2,%3}, {%4,%5,%6,%7}, {%8,%9}, {%0,%1,%2,%3};" \
        : "+f"((d)[0]), "+f"((d)[1]), "+f"((d)[2]), "+f"((d)[3]) \
        : "r"((a)[0]), "r"((a)[1]), "r"((a)[2]), "r"((a)[3]), \
          "r"((bb)[0]), "r"((bb)[1]))
#define MMAB(d, a, bb) \
    asm volatile("mma.sync.aligned.m16n8k16.row.col.f32.bf16.bf16.f32 " \
        "{%0,%1,%2,%3}, {%4,%5,%6,%7}, {%8,%9}, {%0,%1,%2,%3};" \
        : "+f"((d)[0]), "+f"((d)[1]), "+f"((d)[2]), "+f"((d)[3]) \
        : "r"((a)[0]), "r"((a)[1]), "r"((a)[2]), "r"((a)[3]), \
          "r"((bb)[0]), "r"((bb)[1]))

__device__ __forceinline__ uint32_t swb(int m, uint32_t c) {
    return (uint32_t)(m * 128) + ((c ^ (uint32_t)(m & 7)) << 4);
}

// ===========================================================================
// bf16x3 GEMM: D[128x128]=A(128,256)@B(128,256)^T.
// MODE 0+SYMM: energy + mirror + fused softmax partials.
// MODE 6: feat=x+relu(BN(acc+bias)) -> fused query partials (pmg=Wp, psg=q).
// MODE 7: combined projection: bj<2 -> Yqkt bf16 planes (B=Wqk);
//         bj>=2 -> Yv = tf32(acc+bias[col]) written transposed (B=Wv via
//         pmg/psg-cast pointers).
// ===========================================================================
template<int MODE, bool SYMM>
__global__ __launch_bounds__(256, 2)
void mma3bf(const u16* __restrict__ Ah, const u16* __restrict__ Al, size_t sA, int lda,
            const u16* __restrict__ Bh, const u16* __restrict__ Bl, size_t sB, int ldb,
            float* __restrict__ Out, u16* __restrict__ Oh, u16* __restrict__ Ol,
            size_t sC, int ldc,
            const float* __restrict__ bias, const float* __restrict__ gamma,
            const float* __restrict__ beta, const float* __restrict__ xres,
            float* __restrict__ pmg, float* __restrict__ psg)
{
    extern __shared__ char DSM[];
    constexpr int STAGE = 32768;
    constexpr int NIT = CH / 32;

    const int b = blockIdx.z;
    int bi, bj;
    if (SYMM) {
        int t = blockIdx.x;
        bi = 0;
        while (t >= 16 - bi) { t -= 16 - bi; bi++; }
        bj = bi + t;
    } else { bi = blockIdx.x; bj = blockIdx.y; }
    const bool isYv = (MODE == 7) && (bj >= 2);
    const int a0 = bi * 128;
    const int boff = (MODE == 7) ? ((bj & 1) * 128) : bj * 128;

    const u16* BhP = isYv ? (const u16*)pmg : Bh;
    const u16* BlP = isYv ? (const u16*)psg : Bl;
    const u16* Ahr = Ah + (size_t)b * sA + (size_t)a0 * lda;
    const u16* Alr = Al + (size_t)b * sA + (size_t)a0 * lda;
    const u16* Bhr = BhP + (size_t)b * sB + (size_t)boff * ldb;
    const u16* Blr = BlP + (size_t)b * sB + (size_t)boff * ldb;
    const int tid = threadIdx.x, lane = tid & 31;
    const int wm = (tid >> 5) >> 2, wn = (tid >> 5) & 3;
    const uint32_t sbase = smem_u32(DSM);

    float acc[4][4][4];
#pragma unroll
    for (int i = 0; i < 4; i++)
#pragma unroll
        for (int j = 0; j < 4; j++)
#pragma unroll
            for (int k = 0; k < 4; k++) acc[i][j][k] = 0.f;

    const int fm = tid >> 1;
    const int fc = (tid & 1) * 2;

    auto fill = [&](int it) {
        const int k0 = it * 32;
        const uint32_t st = sbase + (it % 3) * STAGE;
#pragma unroll
        for (int i = 0; i < 2; i++) {
            uint32_t c = (uint32_t)(fc + i);
            size_t go = (size_t)fm * lda + k0 + (fc + i) * 8;
            cp16(st + swb(fm, c),     Ahr + go);
            cp16(st + swb(fm, c + 4), Alr + go);
            size_t gob = (size_t)fm * ldb + k0 + (fc + i) * 8;
            cp16(st + 16384 + swb(fm, c),     Bhr + gob);
            cp16(st + 16384 + swb(fm, c + 4), Blr + gob);
        }
        CP_COMMIT();
    };

    fill(0);
    fill(1);
    for (int it = 0; it < NIT; it++) {
        CP_WAIT1();
        __syncthreads();
        if (it + 2 < NIT) fill(it + 2); else CP_COMMIT();

        const uint32_t AT = sbase + (it % 3) * STAGE, BT = AT + 16384;
#pragma unroll
        for (int ks = 0; ks < 2; ks++) {
            const uint32_t ca = (uint32_t)(ks * 2 + (lane >> 4));
            const uint32_t cbg = (uint32_t)(ks * 2 + ((lane & 8) >> 3));
            const int ra = wm * 64 + (lane & 15);
            const int rb = wn * 32 + (lane & 7) + ((lane >> 4) << 3);
            uint32_t ah[4][4], bh[4][2];
#pragma unroll
            for (int mt = 0; mt < 4; mt++) {
                int r = ra + mt * 16;
                LDSM_X4(ah[mt][0], ah[mt][1], ah[mt][2], ah[mt][3], AT + swb(r, ca));
            }
#pragma unroll
            for (int np = 0; np < 2; np++) {
                int r = rb + np * 16;
                LDSM_X4(bh[2 * np][0], bh[2 * np][1], bh[2 * np + 1][0], bh[2 * np + 1][1],
                        BT + swb(r, cbg));
            }
#pragma unroll
            for (int mt = 0; mt < 4; mt++)
#pragma unroll
                for (int nt = 0; nt < 4; nt++) MMAB(acc[mt][nt], ah[mt], bh[nt]);
            uint32_t bl[4][2];
#pragma unroll
            for (int np = 0; np < 2; np++) {
                int r = rb + np * 16;
                LDSM_X4(bl[2 * np][0], bl[2 * np][1], bl[2 * np + 1][0], bl[2 * np + 1][1],
                        BT + swb(r, cbg + 4));
            }
#pragma unroll
            for (int mt = 0; mt < 4; mt++)
#pragma unroll
                for (int nt = 0; nt < 4; nt++) MMAB(acc[mt][nt], ah[mt], bl[nt]);
            uint32_t al[4][4];
#pragma unroll
            for (int mt = 0; mt < 4; mt++) {
                int r = ra + mt * 16;
                LDSM_X4(al[mt][0], al[mt][1], al[mt][2], al[mt][3], AT + swb(r, ca + 4));
            }
#pragma unroll
            for (int mt = 0; mt < 4; mt++)
#pragma unroll
                for (int nt = 0; nt < 4; nt++) MMAB(acc[mt][nt], al[mt], bh[nt]);
        }
        __syncthreads();
    }
    CP_WAIT0();
    __syncthreads();

    const int gid = lane >> 2, tig = lane & 3;
    const float bns = 0.9999950000374996f;
    float* ftile = (float*)DSM;
#pragma unroll
    for (int mt = 0; mt < 4; mt++) {
        int r0 = a0 + wm * 64 + mt * 16 + gid;
        int r1 = r0 + 8;
#pragma unroll
        for (int nt = 0; nt < 4; nt++) {
            int c = boff + wn * 32 + nt * 8 + 2 * tig;
            if (MODE == 0) {
                float* Ob = Out + (size_t)b * sC;
                *(float2*)(Ob + (size_t)r0 * ldc + c) = make_float2(acc[mt][nt][0], acc[mt][nt][1]);
                *(float2*)(Ob + (size_t)r1 * ldc + c) = make_float2(acc[mt][nt][2], acc[mt][nt][3]);
            } else if (MODE == 7) {
                if (!isYv) {
                    u16 h[4], l[4];
#pragma unroll
                    for (int q = 0; q < 4; q++) bf16split(acc[mt][nt][q], h[q], l[q]);
                    u16* OhB = Oh + (size_t)b * sA;
                    u16* OlB = Ol + (size_t)b * sA;
                    int cc = bj * 128 + wn * 32 + nt * 8 + 2 * tig;
                    *(uint32_t*)(OhB + (size_t)r0 * lda + cc) = (uint32_t)h[0] | ((uint32_t)h[1] << 16);
                    *(uint32_t*)(OhB + (size_t)r1 * lda + cc) = (uint32_t)h[2] | ((uint32_t)h[3] << 16);
                    *(uint32_t*)(OlB + (size_t)r0 * lda + cc) = (uint32_t)l[0] | ((uint32_t)l[1] << 16);
                    *(uint32_t*)(OlB + (size_t)r1 * lda + cc) = (uint32_t)l[2] | ((uint32_t)l[3] << 16);
                } else {
                    float b0 = bias[c], b1 = bias[c + 1];
                    int rl0 = wm * 64 + mt * 16 + gid;
                    int cl = wn * 32 + nt * 8 + 2 * tig;
                    ftile[rl0 * 129 + cl]           = __uint_as_float(f2tf32(acc[mt][nt][0] + b0));
                    ftile[rl0 * 129 + cl + 1]       = __uint_as_float(f2tf32(acc[mt][nt][1] + b1));
                    ftile[(rl0 + 8) * 129 + cl]     = __uint_as_float(f2tf32(acc[mt][nt][2] + b0));
                    ftile[(rl0 + 8) * 129 + cl + 1] = __uint_as_float(f2tf32(acc[mt][nt][3] + b1));
                }
            } else {   // MODE 6
                float bb0 = bias[r0], g0 = gamma[r0], be0 = beta[r0];
                float bb1 = bias[r1], g1 = gamma[r1], be1 = beta[r1];
                const float* xb = xres + (size_t)b * CH * NQ;
                float2 x0 = *(const float2*)(xb + (size_t)r0 * NQ + c);
                float2 x1 = *(const float2*)(xb + (size_t)r1 * NQ + c);
                float v0 = (acc[mt][nt][0] + bb0) * bns * g0 + be0;
                float v1 = (acc[mt][nt][1] + bb0) * bns * g0 + be0;
                float v2 = (acc[mt][nt][2] + bb1) * bns * g1 + be1;
                float v3 = (acc[mt][nt][3] + bb1) * bns * g1 + be1;
                int rl0 = wm * 64 + mt * 16 + gid;
                int cl = wn * 32 + nt * 8 + 2 * tig;
                ftile[rl0 * 129 + cl]           = x0.x + fmaxf(v0, 0.f);
                ftile[rl0 * 129 + cl + 1]       = x0.y + fmaxf(v1, 0.f);
                ftile[(rl0 + 8) * 129 + cl]     = x1.x + fmaxf(v2, 0.f);
                ftile[(rl0 + 8) * 129 + cl + 1] = x1.y + fmaxf(v3, 0.f);
            }
        }
    }

    if (MODE == 7) {
        if (isYv) {
            __syncthreads();
            float* Ob = Out + (size_t)b * sC;
#pragma unroll 4
            for (int i = 0; i < 64; i++) {
                int idx = tid + i * 256;
                int rw = idx >> 7, cl = idx & 127;
                Ob[(size_t)(boff + rw) * ldc + a0 + cl] = ftile[cl * 129 + rw];
            }
        }
        return;
    }

    if (MODE == 6) {
        __syncthreads();
        const float* Wp = (const float*)pmg;
        float* qout = psg;
        const int nl = tid & 127, hf = tid >> 7;
        float q0 = 0.f, q1 = 0.f, q2 = 0.f;
#pragma unroll 8
        for (int cc = 0; cc < 64; cc++) {
            int cg = a0 + hf * 64 + cc;
            float fv = ftile[(hf * 64 + cc) * 129 + nl];
            q0 = fmaf(Wp[cg], fv, q0);
            q1 = fmaf(Wp[CH + cg], fv, q1);
            q2 = fmaf(Wp[2 * CH + cg], fv, q2);
        }
        int ng = boff + nl;
        atomicAdd(&qout[((size_t)b * 3) * NQ + ng], q0);
        atomicAdd(&qout[((size_t)b * 3 + 1) * NQ + ng], q1);
        atomicAdd(&qout[((size_t)b * 3 + 2) * NQ + ng], q2);
        return;
    }

    if (SYMM) {
        __syncthreads();
        float* pmR = (float*)DSM;
        float* psR = pmR + 512;
        float* pmC = psR + 512;
        float* psC = pmC + 512;
#pragma unroll
        for (int mt = 0; mt < 4; mt++)
#pragma unroll
            for (int h = 0; h < 2; h++) {
                float mx = -1e30f;
#pragma unroll
                for (int nt = 0; nt < 4; nt++) {
                    mx = fmaxf(mx, acc[mt][nt][h * 2]);
                    mx = fmaxf(mx, acc[mt][nt][h * 2 + 1]);
                }
                float sm = 0.f;
#pragma unroll
                for (int nt = 0; nt < 4; nt++) {
                    sm += __expf(acc[mt][nt][h * 2]     - mx);
                    sm += __expf(acc[mt][nt][h * 2 + 1] - mx);
                }
#pragma unroll
                for (int off = 1; off <= 2; off <<= 1) {
                    float om = __shfl_xor_sync(~0u, mx, off);
                    float os = __shfl_xor_sync(~0u, sm, off);
                    float nm = fmaxf(mx, om);
                    sm = sm * __expf(mx - nm) + os * __expf(om - nm);
                    mx = nm;
                }
                if (tig == 0) {
                    int rl = wm * 64 + mt * 16 + gid + h * 8;
                    pmR[rl * 4 + wn] = mx;
                    psR[rl * 4 + wn] = sm;
                }
            }
        if (bi != bj) {
#pragma unroll
            for (int nt = 0; nt < 4; nt++)
#pragma unroll
                for (int q = 0; q < 2; q++) {
                    float mx = -1e30f;
#pragma unroll
                    for (int mt = 0; mt < 4; mt++) {
                        mx = fmaxf(mx, acc[mt][nt][q]);
                        mx = fmaxf(mx, acc[mt][nt][q + 2]);
                    }
                    float sm = 0.f;
#pragma unroll
                    for (int mt = 0; mt < 4; mt++) {
                        sm += __expf(acc[mt][nt][q]     - mx);
                        sm += __expf(acc[mt][nt][q + 2] - mx);
                    }
#pragma unroll
                    for (int off = 4; off <= 16; off <<= 1) {
                        float om = __shfl_xor_sync(~0u, mx, off);
                        float os = __shfl_xor_sync(~0u, sm, off);
                        float nm = fmaxf(mx, om);
                        sm = sm * __expf(mx - nm) + os * __expf(om - nm);
                        mx = nm;
                    }
                    if (gid == 0) {
                        int cl = wn * 32 + nt * 8 + 2 * tig + q;
                        pmC[cl * 4 + wm] = mx;
                        psC[cl * 4 + wm] = sm;
                    }
                }
        }
        __syncthreads();
        if (tid < 128) {
            float mx = pmR[tid * 4], sm = psR[tid * 4];
#pragma unroll
            for (int w = 1; w < 4; w++) {
                float om = pmR[tid * 4 + w], os = psR[tid * 4 + w];
                float nm = fmaxf(mx, om);
                sm = sm * __expf(mx - nm) + os * __expf(om - nm);
                mx = nm;
            }
            pmg[((size_t)(b * 16 + bj)) * NQ + a0 + tid] = mx;
            psg[((size_t)(b * 16 + bj)) * NQ + a0 + tid] = sm;
        } else if (bi != bj) {
            int cl = tid - 128;
            float mx = pmC[cl * 4], sm = psC[cl * 4];
#pragma unroll
            for (int w = 1; w < 4; w++) {
                float om = pmC[cl * 4 + w], os = psC[cl * 4 + w];
                float nm = fmaxf(mx, om);
                sm = sm * __expf(mx - nm) + os * __expf(om - nm);
                mx = nm;
            }
            pmg[((size_t)(b * 16 + bi)) * NQ + boff + cl] = mx;
            psg[((size_t)(b * 16 + bi)) * NQ + boff + cl] = sm;
        }

        if (bi == bj) return;
        __syncthreads();
        float* sm2 = (float*)DSM;
        float* Ob = Out + (size_t)b * sC;
#pragma unroll
        for (int mt = 0; mt < 4; mt++) {
            int rl0 = wm * 64 + mt * 16 + gid;
#pragma unroll
            for (int nt = 0; nt < 4; nt++) {
                int cl = wn * 32 + nt * 8 + 2 * tig;
                sm2[rl0 * 129 + cl]           = acc[mt][nt][0];
                sm2[rl0 * 129 + cl + 1]       = acc[mt][nt][1];
                sm2[(rl0 + 8) * 129 + cl]     = acc[mt][nt][2];
                sm2[(rl0 + 8) * 129 + cl + 1] = acc[mt][nt][3];
            }
        }
        __syncthreads();
#pragma unroll 4
        for (int i = 0; i < 64; i++) {
            int idx = tid + i * 256;
            int rw = idx >> 7, cl = idx & 127;
            Ob[(size_t)(boff + rw) * ldc + a0 + cl] = sm2[cl * 129 + rw];
        }
    }
}

__global__ __launch_bounds__(256)
void stat_combine(const float* __restrict__ pm, const float* __restrict__ ps,
                  float* __restrict__ rmax, float* __restrict__ rinv)
{
    int row = blockIdx.x * 256 + threadIdx.x;
    int b = row >> 11, r = row & (NQ - 1);
    const float* pmb = pm + (size_t)b * 16 * NQ + r;
    const float* psb = ps + (size_t)b * 16 * NQ + r;
    float mx = -1e30f;
#pragma unroll
    for (int j = 0; j < 16; j++) mx = fmaxf(mx, pmb[(size_t)j * NQ]);
    float s = 0.f;
#pragma unroll
    for (int j = 0; j < 16; j++)
        s += psb[(size_t)j * NQ] * __expf(pmb[(size_t)j * NQ] - mx);
    rmax[row] = mx;
    rinv[row] = 1.f / s;
}

// ===========================================================================
// xr (unchanged from R15): 1xTF32, 64m x 256c tiles, exp computed once.
// ===========================================================================
__global__ __launch_bounds__(256, 2)
void mma_xr(const float* __restrict__ energy, const float* __restrict__ Yv,
            const float* __restrict__ rmax, const float* __restrict__ rinv,
            const u16* __restrict__ xTh, const u16* __restrict__ xTl,
            u16* __restrict__ Outh, u16* __restrict__ Outl)
{
    extern __shared__ char DSM[];
    constexpr int STAGE = 40960;
    constexpr int NIT = NQ / 32;

    const int b = blockIdx.z;
    const int a0 = blockIdx.x * 64;
    const float* Eb = energy + (size_t)b * NQ * NQ;
    const float* Br = Yv + (size_t)b * CH * NQ;
    const int tid = threadIdx.x, lane = tid & 31;
    const int wm = (tid >> 5) >> 2, wn = (tid >> 5) & 3;
    const uint32_t sbase = smem_u32(DSM);

    float acc[2][8][4];
#pragma unroll
    for (int i = 0; i < 2; i++)
#pragma unroll
        for (int j = 0; j < 8; j++)
#pragma unroll
            for (int k = 0; k < 4; k++) acc[i][j][k] = 0.f;
    float csum = 0.f;

    auto fill = [&](int it) {
        const int k0 = it * 32;
        const uint32_t st = sbase + (it & 1) * STAGE;
        char* stc = DSM + (it & 1) * STAGE;
#pragma unroll
        for (int i = 0; i < 2; i++) {
            int idx = tid + i * 256;
            int m = idx & 63, ng = idx >> 6;
            const float* ep = Eb + (size_t)(k0 + ng * 4) * NQ + a0 + m;
            int nb = b * NQ + k0 + ng * 4;
            float4 vs;
            vs.x = __expf(ep[0]              - rmax[nb + 0]) * rinv[nb + 0];
            vs.y = __expf(ep[(size_t)NQ]     - rmax[nb + 1]) * rinv[nb + 1];
            vs.z = __expf(ep[(size_t)2 * NQ] - rmax[nb + 2]) * rinv[nb + 2];
            vs.w = __expf(ep[(size_t)3 * NQ] - rmax[nb + 3]) * rinv[nb + 3];
            csum += vs.x + vs.y + vs.z + vs.w;
            uint4 h;
            h.x = f2tf32(vs.x); h.y = f2tf32(vs.y); h.z = f2tf32(vs.z); h.w = f2tf32(vs.w);
            uint32_t off = (uint32_t)(m * 128 + ((ng * 16) ^ ((m & 7) * 16)));
            *(uint4*)(stc + off) = h;
        }
#pragma unroll
        for (int i = 0; i < 8; i++) {
            int idx = tid + i * 256;
            int r = idx >> 3, j = idx & 7;
            uint32_t off = (uint32_t)(r * 128 + ((j * 16) ^ ((r & 7) * 16)));
            cp16(st + 8192 + off, Br + (size_t)r * NQ + k0 + j * 4);
        }
        CP_COMMIT();
    };

    fill(0);
    for (int it = 0; it < NIT; it++) {
        if (it + 1 < NIT) fill(it + 1); else CP_COMMIT();
        CP_WAIT1();
        __syncthreads();

        const uint32_t AH = sbase + (it & 1) * STAGE, BH = AH + 8192;
#pragma unroll
        for (int ks = 0; ks < 4; ks++) {
            uint32_t ah[2][4], bh[8][2];
            const uint32_t ca = (uint32_t)(ks * 32 + (lane & 16));
            const int ra = wm * 32 + (lane & 15);
#pragma unroll
            for (int mt = 0; mt < 2; mt++) {
                int r = ra + mt * 16;
                uint32_t o = (uint32_t)(r * 128) + (ca ^ (uint32_t)((r & 7) * 16));
                LDSM_X4(ah[mt][0], ah[mt][1], ah[mt][2], ah[mt][3], AH + o);
            }
            const uint32_t cb = (uint32_t)(ks * 32 + ((lane & 8) << 1));
            const int rbb = wn * 64 + (lane & 7) + ((lane & 16) >> 1);
#pragma unroll
            for (int np = 0; np < 4; np++) {
                int r = rbb + np * 16;
                uint32_t o = (uint32_t)(r * 128) + (cb ^ (uint32_t)((r & 7) * 16));
                LDSM_X4(bh[2 * np][0], bh[2 * np][1], bh[2 * np + 1][0], bh[2 * np + 1][1], BH + o);
            }
#pragma unroll
            for (int mt = 0; mt < 2; mt++)
#pragma unroll
                for (int nt = 0; nt < 8; nt++) MMAT(acc[mt][nt], ah[mt], bh[nt]);
        }
        __syncthreads();
    }
    CP_WAIT0();
    __syncthreads();

    float* csA = (float*)DSM;
    csA[tid] = csum;
    __syncthreads();

    const int gid = lane >> 2, tig = lane & 3;
#pragma unroll
    for (int mt = 0; mt < 2; mt++) {
        int lm0 = wm * 32 + mt * 16 + gid;
        int r0 = a0 + lm0, r1 = r0 + 8;
        float inv0 = 1.f / (1e-9f + csA[lm0] + csA[lm0 + 64] + csA[lm0 + 128] + csA[lm0 + 192]);
        float inv1 = 1.f / (1e-9f + csA[lm0 + 8] + csA[lm0 + 72] + csA[lm0 + 136] + csA[lm0 + 200]);
        const u16* xh0 = xTh + ((size_t)b * NQ + r0) * CH;
        const u16* xl0 = xTl + ((size_t)b * NQ + r0) * CH;
        const u16* xh1 = xTh + ((size_t)b * NQ + r1) * CH;
        const u16* xl1 = xTl + ((size_t)b * NQ + r1) * CH;
        u16* oh0 = Outh + ((size_t)b * NQ + r0) * CH;
        u16* oh1 = Outh + ((size_t)b * NQ + r1) * CH;
        u16* ol0 = Outl + ((size_t)b * NQ + r0) * CH;
        u16* ol1 = Outl + ((size_t)b * NQ + r1) * CH;
#pragma unroll
        for (int nt = 0; nt < 8; nt++) {
            int c = wn * 64 + nt * 8 + 2 * tig;
            uint32_t hw0 = *(const uint32_t*)(xh0 + c), lw0 = *(const uint32_t*)(xl0 + c);
            uint32_t hw1 = *(const uint32_t*)(xh1 + c), lw1 = *(const uint32_t*)(xl1 + c);
            float d0 = bfpair(hw0, lw0, 0) - acc[mt][nt][0] * inv0;
            float d1 = bfpair(hw0, lw0, 1) - acc[mt][nt][1] * inv0;
            float d2 = bfpair(hw1, lw1, 0) - acc[mt][nt][2] * inv1;
            float d3 = bfpair(hw1, lw1, 1) - acc[mt][nt][3] * inv1;
            u16 h0, l0, h1, l1, h2, l2, h3, l3;
            bf16split(d0, h0, l0); bf16split(d1, h1, l1);
            bf16split(d2, h2, l2); bf16split(d3, h3, l3);
            *(uint32_t*)(oh0 + c) = (uint32_t)h0 | ((uint32_t)h1 << 16);
            *(uint32_t*)(oh1 + c) = (uint32_t)h2 | ((uint32_t)h3 << 16);
            *(uint32_t*)(ol0 + c) = (uint32_t)l0 | ((uint32_t)l1 << 16);
            *(uint32_t*)(ol1 + c) = (uint32_t)l2 | ((uint32_t)l3 << 16);
        }
    }
}

__global__ __launch_bounds__(256)
void transpose_x(const float* __restrict__ x, u16* __restrict__ xTh, u16* __restrict__ xTl)
{
    __shared__ float tl[32][33];
    const int b = blockIdx.z;
    const int n0 = blockIdx.x * 32, c0 = blockIdx.y * 32;
    const int tx = threadIdx.x & 31, ty = threadIdx.x >> 5;
#pragma unroll
    for (int i = 0; i < 4; i++)
        tl[ty + i * 8][tx] = x[(size_t)b * CH * NQ + (size_t)(c0 + ty + i * 8) * NQ + n0 + tx];
    __syncthreads();
#pragma unroll
    for (int i = 0; i < 4; i++) {
        float v = tl[tx][ty + i * 8];
        size_t o = (size_t)b * NQ * CH + (size_t)(n0 + ty + i * 8) * CH + c0 + tx;
        u16 h, l;
        bf16split(v, h, l);
        xTh[o] = h; xTl[o] = l;
    }
}

__global__ void split_w3(const float* __restrict__ w0, u16* __restrict__ h0, u16* __restrict__ l0,
                         const float* __restrict__ w1, u16* __restrict__ h1, u16* __restrict__ l1,
                         const float* __restrict__ w2, u16* __restrict__ h2, u16* __restrict__ l2)
{
    int i = blockIdx.x * 256 + threadIdx.x;
    int which = i >> 16, j = i & 65535;
    const float* w = which == 0 ? w0 : (which == 1 ? w1 : w2);
    u16* h = which == 0 ? h0 : (which == 1 ? h1 : h2);
    u16* l = which == 0 ? l0 : (which == 1 ? l1 : l2);
    u16 hh, ll;
    bf16split(w[j], hh, ll);
    h[j] = hh; l[j] = ll;
}

__global__ void zero_q(float* __restrict__ q)
{
    int i = blockIdx.x * 256 + threadIdx.x;
    q[i] = 0.f;
}

__global__ __launch_bounds__(256)
void softproj_kernel(const float* __restrict__ pc, const float* __restrict__ query,
                     const float* __restrict__ bp,
                     const float* __restrict__ temp, float* __restrict__ out)
{
    __shared__ float spx[MPTS], spy[MPTS], spz[MPTS];
    const int b = blockIdx.x;
    const float* p = pc + (size_t)b * 3 * MPTS;
    for (int i = threadIdx.x; i < MPTS; i += 256) {
        spx[i] = p[i]; spy[i] = p[MPTS + i]; spz[i] = p[2 * MPTS + i];
    }
    __syncthreads();

    const float t = temp[0];
    const float invsig = 1.f / (fmaxf(t * t, 1e-4f) + 1e-8f);
    const float bp0 = bp[0], bp1 = bp[1], bp2 = bp[2];
    const int warp = threadIdx.x >> 5, lane = threadIdx.x & 31;
    const int qbase = blockIdx.y * 64;

    for (int qq = 0; qq < 8; ++qq) {
        const int n = qbase + warp * 8 + qq;
        const float qx = query[((size_t)b * 3) * NQ + n] + bp0;
        const float qy = query[((size_t)b * 3 + 1) * NQ + n] + bp1;
        const float qz = query[((size_t)b * 3 + 2) * NQ + n] + bp2;

        float d[KNN]; int idx[KNN];
#pragma unroll
        for (int i = 0; i < KNN; i++) { d[i] = 1e30f; idx[i] = 0; }
        for (int m = lane; m < MPTS; m += 32) {
            float dx = spx[m] - qx, dy = spy[m] - qy, dz = spz[m] - qz;
            float dd = fmaf(dx, dx, fmaf(dy, dy, dz * dz));
            if (dd < d[KNN - 1]) {
                d[KNN - 1] = dd; idx[KNN - 1] = m;
#pragma unroll
                for (int j = KNN - 1; j > 0; --j)
                    if (d[j] < d[j - 1]) {
                        float td = d[j]; d[j] = d[j - 1]; d[j - 1] = td;
                        int ti = idx[j]; idx[j] = idx[j - 1]; idx[j - 1] = ti;
                    }
            }
        }
        float wsum = 0.f, ox = 0.f, oy = 0.f, oz = 0.f, dmin = 0.f;
#pragma unroll
        for (int k = 0; k < KNN; k++) {
            float cd = d[0]; int ci = idx[0];
#pragma unroll
            for (int off = 16; off; off >>= 1) {
                float od = __shfl_xor_sync(~0u, cd, off);
                int   oi = __shfl_xor_sync(~0u, ci, off);
                if (od < cd || (od == cd && oi < ci)) { cd = od; ci = oi; }
            }
            if (k == 0) dmin = cd;
            float w = __expf(-(cd - dmin) * invsig);
            wsum += w;
            ox = fmaf(w, spx[ci], ox); oy = fmaf(w, spy[ci], oy); oz = fmaf(w, spz[ci], oz);
            bool iwin = (d[0] == cd && idx[0] == ci);
            unsigned bal = __ballot_sync(~0u, iwin);
            if (lane == (__ffs(bal) - 1)) {
#pragma unroll
                for (int j = 0; j < KNN - 1; j++) { d[j] = d[j + 1]; idx[j] = idx[j + 1]; }
                d[KNN - 1] = 1e30f; idx[KNN - 1] = 0;
            }
        }
        if (lane == 0) {
            float inv = 1.f / wsum;
            out[((size_t)b * 3) * NQ + n] = ox * inv;
            out[((size_t)b * 3 + 1) * NQ + n] = oy * inv;
            out[((size_t)b * 3 + 2) * NQ + n] = oz * inv;
        }
    }
}

// ---------------------------------------------------------------------------
extern "C" void kernel_launch(void* const* d_in, const int* in_sizes, int n_in,
                              void* d_out, int out_size)
{
    const float* x     = (const float*)d_in[0];
    const float* pc    = (const float*)d_in[1];
    const float* Wqk   = (const float*)d_in[2];
    const float* Wv    = (const float*)d_in[3];
    const float* bv    = (const float*)d_in[4];
    const float* Wt    = (const float*)d_in[5];
    const float* bt    = (const float*)d_in[6];
    const float* gamma = (const float*)d_in[7];
    const float* beta  = (const float*)d_in[8];
    const float* Wp    = (const float*)d_in[9];
    const float* bp    = (const float*)d_in[10];
    const float* temp  = (const float*)d_in[11];
    float* out = (float*)d_out;

    float *Yv, *energy, *pm, *ps, *rmx, *rin, *query;
    u16 *xTh, *xTl, *Wqkh, *Wqkl, *Wvh, *Wvl, *Wth, *Wtl;
    u16 *Yqkth, *Yqktl, *dbufTh, *dbufTl;
    cudaGetSymbolAddress((void**)&xTh,   g_xTh);
    cudaGetSymbolAddress((void**)&xTl,   g_xTl);
    cudaGetSymbolAddress((void**)&Wqkh,  g_Wqkh);
    cudaGetSymbolAddress((void**)&Wqkl,  g_Wqkl);
    cudaGetSymbolAddress((void**)&Wvh,   g_Wvh);
    cudaGetSymbolAddress((void**)&Wvl,   g_Wvl);
    cudaGetSymbolAddress((void**)&Wth,   g_Wth);
    cudaGetSymbolAddress((void**)&Wtl,   g_Wtl);
    cudaGetSymbolAddress((void**)&Yqkth, g_Yqkth);
    cudaGetSymbolAddress((void**)&Yqktl, g_Yqktl);
    cudaGetSymbolAddress((void**)&Yv,    g_Yv);
    cudaGetSymbolAddress((void**)&energy,g_energy);
    cudaGetSymbolAddress((void**)&pm,    g_pm);
    cudaGetSymbolAddress((void**)&ps,    g_ps);
    cudaGetSymbolAddress((void**)&rmx,   g_rmax);
    cudaGetSymbolAddress((void**)&rin,   g_rinv);
    cudaGetSymbolAddress((void**)&dbufTh,g_dbufTh);
    cudaGetSymbolAddress((void**)&dbufTl,g_dbufTl);
    cudaGetSymbolAddress((void**)&query, g_query);

    const size_t CHNQ = (size_t)CH * NQ;
    const size_t NQNQ = (size_t)NQ * NQ;
    const size_t NQCH = (size_t)NQ * CH;

    cudaFuncSetAttribute(mma3bf<7, false>, cudaFuncAttributeMaxDynamicSharedMemorySize, 98304);
    cudaFuncSetAttribute(mma3bf<0, true >, cudaFuncAttributeMaxDynamicSharedMemorySize, 98304);
    cudaFuncSetAttribute(mma3bf<6, false>, cudaFuncAttributeMaxDynamicSharedMemorySize, 98304);
    cudaFuncSetAttribute(mma_xr, cudaFuncAttributeMaxDynamicSharedMemorySize, 81920);

    dim3 blk(256);
    transpose_x<<<dim3(NQ / 32, CH / 32, BATCH), blk>>>(x, xTh, xTl);
    split_w3<<<768, 256>>>(Wqk, Wqkh, Wqkl, Wv, Wvh, Wvl, Wt, Wth, Wtl);
    zero_q<<<BATCH * 3 * NQ / 256, 256>>>(query);
    // combined: bj<2 Yqkt planes (B=Wqk, out strides sA/lda);
    //           bj>=2 Yv = tf32(xT@Wv^T + bv)^T  (B=Wv via pmg/psg)
    mma3bf<7, false><<<dim3(16, 4, 8), blk, 98304>>>(
        xTh, xTl, NQCH, CH, Wqkh, Wqkl, 0, CH,
        Yv, Yqkth, Yqktl, CHNQ, NQ, bv, nullptr, nullptr, nullptr,
        (float*)Wvh, (float*)Wvl);
    mma3bf<0, true><<<dim3(136, 1, 8), blk, 98304>>>(
        Yqkth, Yqktl, NQCH, CH, Yqkth, Yqktl, NQCH, CH,
        energy, nullptr, nullptr, NQNQ, NQ, nullptr, nullptr, nullptr, nullptr, pm, ps);
    stat_combine<<<BATCH * NQ / 256, 256>>>(pm, ps, rmx, rin);
    mma_xr<<<dim3(32, 1, 8), blk, 81920>>>(energy, Yv, rmx, rin, xTh, xTl, dbufTh, dbufTl);
    mma3bf<6, false><<<dim3(2, 16, 8), blk, 98304>>>(
        Wth, Wtl, 0, CH, dbufTh, dbufTl, NQCH, CH,
        nullptr, nullptr, nullptr, CHNQ, NQ, bt, gamma, beta, x, (float*)Wp, query);
    softproj_kernel<<<dim3(BATCH, NQ / 64), 256>>>(pc, query, bp, temp, out);
}

// round 17
// speedup vs baseline: 1.0280x; 1.0280x over previous
#include <cuda_runtime.h>
#include <cuda_bf16.h>
#include <math.h>
#include <stdint.h>

#define BATCH 8
#define CH    256
#define NQ    2048
#define MPTS  4096
#define KNN   10

typedef unsigned short u16;

static __device__ u16   g_xTh [(size_t)BATCH * NQ * CH];
static __device__ u16   g_xTl [(size_t)BATCH * NQ * CH];
static __device__ u16   g_Wqkh[CH * CH], g_Wqkl[CH * CH];
static __device__ u16   g_Wvh [CH * CH], g_Wvl [CH * CH];
static __device__ u16   g_Wth [CH * CH], g_Wtl [CH * CH];
static __device__ u16   g_Yqkth[(size_t)BATCH * NQ * CH];
static __device__ u16   g_Yqktl[(size_t)BATCH * NQ * CH];
static __device__ float g_Yv  [(size_t)BATCH * CH * NQ];
static __device__ float g_energy[(size_t)BATCH * NQ * NQ];
static __device__ float g_pm  [(size_t)BATCH * 16 * NQ];
static __device__ float g_ps  [(size_t)BATCH * 16 * NQ];
static __device__ float g_rmax[BATCH * NQ];
static __device__ float g_rinv[BATCH * NQ];
static __device__ u16   g_dbufTh[(size_t)BATCH * NQ * CH];
static __device__ u16   g_dbufTl[(size_t)BATCH * NQ * CH];
static __device__ float g_query[(size_t)BATCH * 3 * NQ];

__device__ __forceinline__ uint32_t smem_u32(const void* p) {
    uint32_t a;
    asm("{ .reg .u64 t; cvta.to.shared.u64 t, %1; cvt.u32.u64 %0, t; }" : "=r"(a) : "l"(p));
    return a;
}
__device__ __forceinline__ uint32_t f2tf32(float f) {
    uint32_t r;
    asm("cvt.rna.tf32.f32 %0, %1;" : "=r"(r) : "f"(f));
    return r;
}
__device__ __forceinline__ void bf16split(float v, u16& h, u16& l) {
    __nv_bfloat16 hb = __float2bfloat16_rn(v);
    h = __bfloat16_as_ushort(hb);
    __nv_bfloat16 lb = __float2bfloat16_rn(v - __bfloat162float(hb));
    l = __bfloat16_as_ushort(lb);
}
__device__ __forceinline__ float bfpair(uint32_t hw, uint32_t lw, int sel) {
    u16 h = (u16)(sel ? (hw >> 16) : (hw & 0xffff));
    u16 l = (u16)(sel ? (lw >> 16) : (lw & 0xffff));
    return __bfloat162float(__ushort_as_bfloat16(h)) +
           __bfloat162float(__ushort_as_bfloat16(l));
}
__device__ __forceinline__ void cp16(uint32_t dst, const void* src) {
    asm volatile("cp.async.ca.shared.global [%0], [%1], 16;" :: "r"(dst), "l"(src) : "memory");
}
#define CP_COMMIT() asm volatile("cp.async.commit_group;" ::: "memory")
#define CP_WAIT1()  asm volatile("cp.async.wait_group 1;" ::: "memory")
#define CP_WAIT0()  asm volatile("cp.async.wait_group 0;" ::: "memory")
#define LDSM_X4(r0, r1, r2, r3, addr) \
    asm volatile("ldmatrix.sync.aligned.m8n8.x4.shared.b16 {%0,%1,%2,%3}, [%4];" \
        : "=r"(r0), "=r"(r1), "=r"(r2), "=r"(r3) : "r"(addr))
#define MMAT(d, a, bb) \
    asm volatile("mma.sync.aligned.m16n8k8.row.col.f32.tf32.tf32.f32 " \
        "{%0,%1,%2,%3}, {%4,%5,%6,%7}, {%8,%9}, {%0,%1,%2,%3};" \
        : "+f"((d)[0]), "+f"((d)[1]), "+f"((d)[2]), "+f"((d)[3]) \
        : "r"((a)[0]), "r"((a)[1]), "r"((a)[2]), "r"((a)[3]), \
          "r"((bb)[0]), "r"((bb)[1]))
#define MMAB(d, a, bb) \
    asm volatile("mma.sync.aligned.m16n8k16.row.col.f32.bf16.bf16.f32 " \
        "{%0,%1,%2,%3}, {%4,%5,%6,%7}, {%8,%9}, {%0,%1,%2,%3};" \
        : "+f"((d)[0]), "+f"((d)[1]), "+f"((d)[2]), "+f"((d)[3]) \
        : "r"((a)[0]), "r"((a)[1]), "r"((a)[2]), "r"((a)[3]), \
          "r"((bb)[0]), "r"((bb)[1]))

__device__ __forceinline__ uint32_t swb(int m, uint32_t c) {
    return (uint32_t)(m * 128) + ((c ^ (uint32_t)(m & 7)) << 4);
}

// ===========================================================================
// bf16x3 GEMM: D[128x128]=A(128,256)@B(128,256)^T  (R15-verified config).
// MODE 0+SYMM: energy + mirror + fused softmax partials.
// MODE 4: bf16 planes. MODE 5: tf32(acc+bias).
// MODE 6: feat=x+relu(BN(acc+bias)) -> fused query partials (pmg=Wp, psg=q).
// ===========================================================================
template<int MODE, bool SYMM>
__global__ __launch_bounds__(256, 2)
void mma3bf(const u16* __restrict__ Ah, const u16* __restrict__ Al, size_t sA, int lda,
            const u16* __restrict__ Bh, const u16* __restrict__ Bl, size_t sB, int ldb,
            float* __restrict__ Out, u16* __restrict__ Oh, u16* __restrict__ Ol,
            size_t sC, int ldc,
            const float* __restrict__ bias, const float* __restrict__ gamma,
            const float* __restrict__ beta, const float* __restrict__ xres,
            float* __restrict__ pmg, float* __restrict__ psg)
{
    extern __shared__ char DSM[];
    constexpr int STAGE = 32768;
    constexpr int NIT = CH / 32;

    const int b = blockIdx.z;
    int bi, bj;
    if (SYMM) {
        int t = blockIdx.x;
        bi = 0;
        while (t >= 16 - bi) { t -= 16 - bi; bi++; }
        bj = bi + t;
    } else { bi = blockIdx.x; bj = blockIdx.y; }
    const int a0 = bi * 128, boff = bj * 128;

    const u16* Ahr = Ah + (size_t)b * sA + (size_t)a0 * lda;
    const u16* Alr = Al + (size_t)b * sA + (size_t)a0 * lda;
    const u16* Bhr = Bh + (size_t)b * sB + (size_t)boff * ldb;
    const u16* Blr = Bl + (size_t)b * sB + (size_t)boff * ldb;
    const int tid = threadIdx.x, lane = tid & 31;
    const int wm = (tid >> 5) >> 2, wn = (tid >> 5) & 3;
    const uint32_t sbase = smem_u32(DSM);

    float acc[4][4][4];
#pragma unroll
    for (int i = 0; i < 4; i++)
#pragma unroll
        for (int j = 0; j < 4; j++)
#pragma unroll
            for (int k = 0; k < 4; k++) acc[i][j][k] = 0.f;

    const int fm = tid >> 1;
    const int fc = (tid & 1) * 2;

    auto fill = [&](int it) {
        const int k0 = it * 32;
        const uint32_t st = sbase + (it % 3) * STAGE;
#pragma unroll
        for (int i = 0; i < 2; i++) {
            uint32_t c = (uint32_t)(fc + i);
            size_t go = (size_t)fm * lda + k0 + (fc + i) * 8;
            cp16(st + swb(fm, c),     Ahr + go);
            cp16(st + swb(fm, c + 4), Alr + go);
            size_t gob = (size_t)fm * ldb + k0 + (fc + i) * 8;
            cp16(st + 16384 + swb(fm, c),     Bhr + gob);
            cp16(st + 16384 + swb(fm, c + 4), Blr + gob);
        }
        CP_COMMIT();
    };

    fill(0);
    fill(1);
    for (int it = 0; it < NIT; it++) {
        CP_WAIT1();
        __syncthreads();
        if (it + 2 < NIT) fill(it + 2); else CP_COMMIT();

        const uint32_t AT = sbase + (it % 3) * STAGE, BT = AT + 16384;
#pragma unroll
        for (int ks = 0; ks < 2; ks++) {
            const uint32_t ca = (uint32_t)(ks * 2 + (lane >> 4));
            const uint32_t cbg = (uint32_t)(ks * 2 + ((lane & 8) >> 3));
            const int ra = wm * 64 + (lane & 15);
            const int rb = wn * 32 + (lane & 7) + ((lane >> 4) << 3);
            uint32_t ah[4][4], bh[4][2];
#pragma unroll
            for (int mt = 0; mt < 4; mt++) {
                int r = ra + mt * 16;
                LDSM_X4(ah[mt][0], ah[mt][1], ah[mt][2], ah[mt][3], AT + swb(r, ca));
            }
#pragma unroll
            for (int np = 0; np < 2; np++) {
                int r = rb + np * 16;
                LDSM_X4(bh[2 * np][0], bh[2 * np][1], bh[2 * np + 1][0], bh[2 * np + 1][1],
                        BT + swb(r, cbg));
            }
#pragma unroll
            for (int mt = 0; mt < 4; mt++)
#pragma unroll
                for (int nt = 0; nt < 4; nt++) MMAB(acc[mt][nt], ah[mt], bh[nt]);
            uint32_t bl[4][2];
#pragma unroll
            for (int np = 0; np < 2; np++) {
                int r = rb + np * 16;
                LDSM_X4(bl[2 * np][0], bl[2 * np][1], bl[2 * np + 1][0], bl[2 * np + 1][1],
                        BT + swb(r, cbg + 4));
            }
#pragma unroll
            for (int mt = 0; mt < 4; mt++)
#pragma unroll
                for (int nt = 0; nt < 4; nt++) MMAB(acc[mt][nt], ah[mt], bl[nt]);
            uint32_t al[4][4];
#pragma unroll
            for (int mt = 0; mt < 4; mt++) {
                int r = ra + mt * 16;
                LDSM_X4(al[mt][0], al[mt][1], al[mt][2], al[mt][3], AT + swb(r, ca + 4));
            }
#pragma unroll
            for (int mt = 0; mt < 4; mt++)
#pragma unroll
                for (int nt = 0; nt < 4; nt++) MMAB(acc[mt][nt], al[mt], bh[nt]);
        }
        __syncthreads();
    }
    CP_WAIT0();
    __syncthreads();

    const int gid = lane >> 2, tig = lane & 3;
    const float bns = 0.9999950000374996f;
    float* ftile = (float*)DSM;
#pragma unroll
    for (int mt = 0; mt < 4; mt++) {
        int r0 = a0 + wm * 64 + mt * 16 + gid;
        int r1 = r0 + 8;
#pragma unroll
        for (int nt = 0; nt < 4; nt++) {
            int c = boff + wn * 32 + nt * 8 + 2 * tig;
            if (MODE == 0) {
                float* Ob = Out + (size_t)b * sC;
                *(float2*)(Ob + (size_t)r0 * ldc + c) = make_float2(acc[mt][nt][0], acc[mt][nt][1]);
                *(float2*)(Ob + (size_t)r1 * ldc + c) = make_float2(acc[mt][nt][2], acc[mt][nt][3]);
            } else if (MODE == 4) {
                u16 h[4], l[4];
#pragma unroll
                for (int q = 0; q < 4; q++) bf16split(acc[mt][nt][q], h[q], l[q]);
                u16* OhB = Oh + (size_t)b * sC;
                u16* OlB = Ol + (size_t)b * sC;
                *(uint32_t*)(OhB + (size_t)r0 * ldc + c) = (uint32_t)h[0] | ((uint32_t)h[1] << 16);
                *(uint32_t*)(OhB + (size_t)r1 * ldc + c) = (uint32_t)h[2] | ((uint32_t)h[3] << 16);
                *(uint32_t*)(OlB + (size_t)r0 * ldc + c) = (uint32_t)l[0] | ((uint32_t)l[1] << 16);
                *(uint32_t*)(OlB + (size_t)r1 * ldc + c) = (uint32_t)l[2] | ((uint32_t)l[3] << 16);
            } else if (MODE == 5) {
                float* Ob = Out + (size_t)b * sC;
                float b0 = bias[r0], b1 = bias[r1];
                *(float2*)(Ob + (size_t)r0 * ldc + c) = make_float2(
                    __uint_as_float(f2tf32(acc[mt][nt][0] + b0)), __uint_as_float(f2tf32(acc[mt][nt][1] + b0)));
                *(float2*)(Ob + (size_t)r1 * ldc + c) = make_float2(
                    __uint_as_float(f2tf32(acc[mt][nt][2] + b1)), __uint_as_float(f2tf32(acc[mt][nt][3] + b1)));
            } else {   // MODE 6
                float bb0 = bias[r0], g0 = gamma[r0], be0 = beta[r0];
                float bb1 = bias[r1], g1 = gamma[r1], be1 = beta[r1];
                const float* xb = xres + (size_t)b * CH * NQ;
                float2 x0 = *(const float2*)(xb + (size_t)r0 * NQ + c);
                float2 x1 = *(const float2*)(xb + (size_t)r1 * NQ + c);
                float v0 = (acc[mt][nt][0] + bb0) * bns * g0 + be0;
                float v1 = (acc[mt][nt][1] + bb0) * bns * g0 + be0;
                float v2 = (acc[mt][nt][2] + bb1) * bns * g1 + be1;
                float v3 = (acc[mt][nt][3] + bb1) * bns * g1 + be1;
                int rl0 = wm * 64 + mt * 16 + gid;
                int cl = wn * 32 + nt * 8 + 2 * tig;
                ftile[rl0 * 129 + cl]           = x0.x + fmaxf(v0, 0.f);
                ftile[rl0 * 129 + cl + 1]       = x0.y + fmaxf(v1, 0.f);
                ftile[(rl0 + 8) * 129 + cl]     = x1.x + fmaxf(v2, 0.f);
                ftile[(rl0 + 8) * 129 + cl + 1] = x1.y + fmaxf(v3, 0.f);
            }
        }
    }

    if (MODE == 6) {
        __syncthreads();
        const float* Wp = (const float*)pmg;
        float* qout = psg;
        const int nl = tid & 127, hf = tid >> 7;
        float q0 = 0.f, q1 = 0.f, q2 = 0.f;
#pragma unroll 8
        for (int cc = 0; cc < 64; cc++) {
            int cg = a0 + hf * 64 + cc;
            float fv = ftile[(hf * 64 + cc) * 129 + nl];
            q0 = fmaf(Wp[cg], fv, q0);
            q1 = fmaf(Wp[CH + cg], fv, q1);
            q2 = fmaf(Wp[2 * CH + cg], fv, q2);
        }
        int ng = boff + nl;
        atomicAdd(&qout[((size_t)b * 3) * NQ + ng], q0);
        atomicAdd(&qout[((size_t)b * 3 + 1) * NQ + ng], q1);
        atomicAdd(&qout[((size_t)b * 3 + 2) * NQ + ng], q2);
        return;
    }

    if (SYMM) {
        __syncthreads();
        float* pmR = (float*)DSM;
        float* psR = pmR + 512;
        float* pmC = psR + 512;
        float* psC = pmC + 512;
#pragma unroll
        for (int mt = 0; mt < 4; mt++)
#pragma unroll
            for (int h = 0; h < 2; h++) {
                float mx = -1e30f;
#pragma unroll
                for (int nt = 0; nt < 4; nt++) {
                    mx = fmaxf(mx, acc[mt][nt][h * 2]);
                    mx = fmaxf(mx, acc[mt][nt][h * 2 + 1]);
                }
                float sm = 0.f;
#pragma unroll
                for (int nt = 0; nt < 4; nt++) {
                    sm += __expf(acc[mt][nt][h * 2]     - mx);
                    sm += __expf(acc[mt][nt][h * 2 + 1] - mx);
                }
#pragma unroll
                for (int off = 1; off <= 2; off <<= 1) {
                    float om = __shfl_xor_sync(~0u, mx, off);
                    float os = __shfl_xor_sync(~0u, sm, off);
                    float nm = fmaxf(mx, om);
                    sm = sm * __expf(mx - nm) + os * __expf(om - nm);
                    mx = nm;
                }
                if (tig == 0) {
                    int rl = wm * 64 + mt * 16 + gid + h * 8;
                    pmR[rl * 4 + wn] = mx;
                    psR[rl * 4 + wn] = sm;
                }
            }
        if (bi != bj) {
#pragma unroll
            for (int nt = 0; nt < 4; nt++)
#pragma unroll
                for (int q = 0; q < 2; q++) {
                    float mx = -1e30f;
#pragma unroll
                    for (int mt = 0; mt < 4; mt++) {
                        mx = fmaxf(mx, acc[mt][nt][q]);
                        mx = fmaxf(mx, acc[mt][nt][q + 2]);
                    }
                    float sm = 0.f;
#pragma unroll
                    for (int mt = 0; mt < 4; mt++) {
                        sm += __expf(acc[mt][nt][q]     - mx);
                        sm += __expf(acc[mt][nt][q + 2] - mx);
                    }
#pragma unroll
                    for (int off = 4; off <= 16; off <<= 1) {
                        float om = __shfl_xor_sync(~0u, mx, off);
                        float os = __shfl_xor_sync(~0u, sm, off);
                        float nm = fmaxf(mx, om);
                        sm = sm * __expf(mx - nm) + os * __expf(om - nm);
                        mx = nm;
                    }
                    if (gid == 0) {
                        int cl = wn * 32 + nt * 8 + 2 * tig + q;
                        pmC[cl * 4 + wm] = mx;
                        psC[cl * 4 + wm] = sm;
                    }
                }
        }
        __syncthreads();
        if (tid < 128) {
            float mx = pmR[tid * 4], sm = psR[tid * 4];
#pragma unroll
            for (int w = 1; w < 4; w++) {
                float om = pmR[tid * 4 + w], os = psR[tid * 4 + w];
                float nm = fmaxf(mx, om);
                sm = sm * __expf(mx - nm) + os * __expf(om - nm);
                mx = nm;
            }
            pmg[((size_t)(b * 16 + bj)) * NQ + a0 + tid] = mx;
            psg[((size_t)(b * 16 + bj)) * NQ + a0 + tid] = sm;
        } else if (bi != bj) {
            int cl = tid - 128;
            float mx = pmC[cl * 4], sm = psC[cl * 4];
#pragma unroll
            for (int w = 1; w < 4; w++) {
                float om = pmC[cl * 4 + w], os = psC[cl * 4 + w];
                float nm = fmaxf(mx, om);
                sm = sm * __expf(mx - nm) + os * __expf(om - nm);
                mx = nm;
            }
            pmg[((size_t)(b * 16 + bi)) * NQ + boff + cl] = mx;
            psg[((size_t)(b * 16 + bi)) * NQ + boff + cl] = sm;
        }

        if (bi == bj) return;
        __syncthreads();
        float* sm2 = (float*)DSM;
        float* Ob = Out + (size_t)b * sC;
#pragma unroll
        for (int mt = 0; mt < 4; mt++) {
            int rl0 = wm * 64 + mt * 16 + gid;
#pragma unroll
            for (int nt = 0; nt < 4; nt++) {
                int cl = wn * 32 + nt * 8 + 2 * tig;
                sm2[rl0 * 129 + cl]           = acc[mt][nt][0];
                sm2[rl0 * 129 + cl + 1]       = acc[mt][nt][1];
                sm2[(rl0 + 8) * 129 + cl]     = acc[mt][nt][2];
                sm2[(rl0 + 8) * 129 + cl + 1] = acc[mt][nt][3];
            }
        }
        __syncthreads();
#pragma unroll 4
        for (int i = 0; i < 64; i++) {
            int idx = tid + i * 256;
            int rw = idx >> 7, cl = idx & 127;
            Ob[(size_t)(boff + rw) * ldc + a0 + cl] = sm2[cl * 129 + rw];
        }
    }
}

__global__ __launch_bounds__(256)
void stat_combine(const float* __restrict__ pm, const float* __restrict__ ps,
                  float* __restrict__ rmax, float* __restrict__ rinv)
{
    int row = blockIdx.x * 256 + threadIdx.x;
    int b = row >> 11, r = row & (NQ - 1);
    const float* pmb = pm + (size_t)b * 16 * NQ + r;
    const float* psb = ps + (size_t)b * 16 * NQ + r;
    float mx = -1e30f;
#pragma unroll
    for (int j = 0; j < 16; j++) mx = fmaxf(mx, pmb[(size_t)j * NQ]);
    float s = 0.f;
#pragma unroll
    for (int j = 0; j < 16; j++)
        s = fmaf(psb[(size_t)j * NQ], __expf(pmb[(size_t)j * NQ] - mx), s);
    rmax[row] = mx;
    rinv[row] = 1.f / s;
}

// ===========================================================================
// xr (R15-verified): 1xTF32, 64m x 256c tiles, exp computed once, 2 CTAs/SM.
// ===========================================================================
__global__ __launch_bounds__(256, 2)
void mma_xr(const float* __restrict__ energy, const float* __restrict__ Yv,
            const float* __restrict__ rmax, const float* __restrict__ rinv,
            const u16* __restrict__ xTh, const u16* __restrict__ xTl,
            u16* __restrict__ Outh, u16* __restrict__ Outl)
{
    extern __shared__ char DSM[];
    constexpr int STAGE = 40960;
    constexpr int NIT = NQ / 32;

    const int b = blockIdx.z;
    const int a0 = blockIdx.x * 64;
    const float* Eb = energy + (size_t)b * NQ * NQ;
    const float* Br = Yv + (size_t)b * CH * NQ;
    const int tid = threadIdx.x, lane = tid & 31;
    const int wm = (tid >> 5) >> 2, wn = (tid >> 5) & 3;
    const uint32_t sbase = smem_u32(DSM);

    float acc[2][8][4];
#pragma unroll
    for (int i = 0; i < 2; i++)
#pragma unroll
        for (int j = 0; j < 8; j++)
#pragma unroll
            for (int k = 0; k < 4; k++) acc[i][j][k] = 0.f;
    float csum = 0.f;

    auto fill = [&](int it) {
        const int k0 = it * 32;
        const uint32_t st = sbase + (it & 1) * STAGE;
        char* stc = DSM + (it & 1) * STAGE;
#pragma unroll
        for (int i = 0; i < 2; i++) {
            int idx = tid + i * 256;
            int m = idx & 63, ng = idx >> 6;
            const float* ep = Eb + (size_t)(k0 + ng * 4) * NQ + a0 + m;
            int nb = b * NQ + k0 + ng * 4;
            float4 vs;
            vs.x = __expf(ep[0]              - rmax[nb + 0]) * rinv[nb + 0];
            vs.y = __expf(ep[(size_t)NQ]     - rmax[nb + 1]) * rinv[nb + 1];
            vs.z = __expf(ep[(size_t)2 * NQ] - rmax[nb + 2]) * rinv[nb + 2];
            vs.w = __expf(ep[(size_t)3 * NQ] - rmax[nb + 3]) * rinv[nb + 3];
            csum += vs.x + vs.y + vs.z + vs.w;
            uint4 h;
            h.x = f2tf32(vs.x); h.y = f2tf32(vs.y); h.z = f2tf32(vs.z); h.w = f2tf32(vs.w);
            uint32_t off = (uint32_t)(m * 128 + ((ng * 16) ^ ((m & 7) * 16)));
            *(uint4*)(stc + off) = h;
        }
#pragma unroll
        for (int i = 0; i < 8; i++) {
            int idx = tid + i * 256;
            int r = idx >> 3, j = idx & 7;
            uint32_t off = (uint32_t)(r * 128 + ((j * 16) ^ ((r & 7) * 16)));
            cp16(st + 8192 + off, Br + (size_t)r * NQ + k0 + j * 4);
        }
        CP_COMMIT();
    };

    fill(0);
    for (int it = 0; it < NIT; it++) {
        if (it + 1 < NIT) fill(it + 1); else CP_COMMIT();
        CP_WAIT1();
        __syncthreads();

        const uint32_t AH = sbase + (it & 1) * STAGE, BH = AH + 8192;
#pragma unroll
        for (int ks = 0; ks < 4; ks++) {
            uint32_t ah[2][4], bh[8][2];
            const uint32_t ca = (uint32_t)(ks * 32 + (lane & 16));
            const int ra = wm * 32 + (lane & 15);
#pragma unroll
            for (int mt = 0; mt < 2; mt++) {
                int r = ra + mt * 16;
                uint32_t o = (uint32_t)(r * 128) + (ca ^ (uint32_t)((r & 7) * 16));
                LDSM_X4(ah[mt][0], ah[mt][1], ah[mt][2], ah[mt][3], AH + o);
            }
            const uint32_t cb = (uint32_t)(ks * 32 + ((lane & 8) << 1));
            const int rbb = wn * 64 + (lane & 7) + ((lane & 16) >> 1);
#pragma unroll
            for (int np = 0; np < 4; np++) {
                int r = rbb + np * 16;
                uint32_t o = (uint32_t)(r * 128) + (cb ^ (uint32_t)((r & 7) * 16));
                LDSM_X4(bh[2 * np][0], bh[2 * np][1], bh[2 * np + 1][0], bh[2 * np + 1][1], BH + o);
            }
#pragma unroll
            for (int mt = 0; mt < 2; mt++)
#pragma unroll
                for (int nt = 0; nt < 8; nt++) MMAT(acc[mt][nt], ah[mt], bh[nt]);
        }
        __syncthreads();
    }
    CP_WAIT0();
    __syncthreads();

    float* csA = (float*)DSM;
    csA[tid] = csum;
    __syncthreads();

    const int gid = lane >> 2, tig = lane & 3;
#pragma unroll
    for (int mt = 0; mt < 2; mt++) {
        int lm0 = wm * 32 + mt * 16 + gid;
        int r0 = a0 + lm0, r1 = r0 + 8;
        float inv0 = 1.f / (1e-9f + csA[lm0] + csA[lm0 + 64] + csA[lm0 + 128] + csA[lm0 + 192]);
        float inv1 = 1.f / (1e-9f + csA[lm0 + 8] + csA[lm0 + 72] + csA[lm0 + 136] + csA[lm0 + 200]);
        const u16* xh0 = xTh + ((size_t)b * NQ + r0) * CH;
        const u16* xl0 = xTl + ((size_t)b * NQ + r0) * CH;
        const u16* xh1 = xTh + ((size_t)b * NQ + r1) * CH;
        const u16* xl1 = xTl + ((size_t)b * NQ + r1) * CH;
        u16* oh0 = Outh + ((size_t)b * NQ + r0) * CH;
        u16* oh1 = Outh + ((size_t)b * NQ + r1) * CH;
        u16* ol0 = Outl + ((size_t)b * NQ + r0) * CH;
        u16* ol1 = Outl + ((size_t)b * NQ + r1) * CH;
#pragma unroll
        for (int nt = 0; nt < 8; nt++) {
            int c = wn * 64 + nt * 8 + 2 * tig;
            uint32_t hw0 = *(const uint32_t*)(xh0 + c), lw0 = *(const uint32_t*)(xl0 + c);
            uint32_t hw1 = *(const uint32_t*)(xh1 + c), lw1 = *(const uint32_t*)(xl1 + c);
            float d0 = bfpair(hw0, lw0, 0) - acc[mt][nt][0] * inv0;
            float d1 = bfpair(hw0, lw0, 1) - acc[mt][nt][1] * inv0;
            float d2 = bfpair(hw1, lw1, 0) - acc[mt][nt][2] * inv1;
            float d3 = bfpair(hw1, lw1, 1) - acc[mt][nt][3] * inv1;
            u16 h0, l0, h1, l1, h2, l2, h3, l3;
            bf16split(d0, h0, l0); bf16split(d1, h1, l1);
            bf16split(d2, h2, l2); bf16split(d3, h3, l3);
            *(uint32_t*)(oh0 + c) = (uint32_t)h0 | ((uint32_t)h1 << 16);
            *(uint32_t*)(oh1 + c) = (uint32_t)h2 | ((uint32_t)h3 << 16);
            *(uint32_t*)(ol0 + c) = (uint32_t)l0 | ((uint32_t)l1 << 16);
            *(uint32_t*)(ol1 + c) = (uint32_t)l2 | ((uint32_t)l3 << 16);
        }
    }
}

__global__ __launch_bounds__(256)
void transpose_x(const float* __restrict__ x, u16* __restrict__ xTh, u16* __restrict__ xTl)
{
    __shared__ float tl[32][33];
    const int b = blockIdx.z;
    const int n0 = blockIdx.x * 32, c0 = blockIdx.y * 32;
    const int tx = threadIdx.x & 31, ty = threadIdx.x >> 5;
#pragma unroll
    for (int i = 0; i < 4; i++)
        tl[ty + i * 8][tx] = x[(size_t)b * CH * NQ + (size_t)(c0 + ty + i * 8) * NQ + n0 + tx];
    __syncthreads();
#pragma unroll
    for (int i = 0; i < 4; i++) {
        float v = tl[tx][ty + i * 8];
        size_t o = (size_t)b * NQ * CH + (size_t)(n0 + ty + i * 8) * CH + c0 + tx;
        u16 h, l;
        bf16split(v, h, l);
        xTh[o] = h; xTl[o] = l;
    }
}

// split 3 weights + zero query in one launch (grid 960)
__global__ void split_w3z(const float* __restrict__ w0, u16* __restrict__ h0, u16* __restrict__ l0,
                          const float* __restrict__ w1, u16* __restrict__ h1, u16* __restrict__ l1,
                          const float* __restrict__ w2, u16* __restrict__ h2, u16* __restrict__ l2,
                          float* __restrict__ q)
{
    int i = blockIdx.x * 256 + threadIdx.x;
    if (i < 3 * CH * CH) {
        int which = i >> 16, j = i & 65535;
        const float* w = which == 0 ? w0 : (which == 1 ? w1 : w2);
        u16* h = which == 0 ? h0 : (which == 1 ? h1 : h2);
        u16* l = which == 0 ? l0 : (which == 1 ? l1 : l2);
        u16 hh, ll;
        bf16split(w[j], hh, ll);
        h[j] = hh; l[j] = ll;
    } else {
        q[i - 3 * CH * CH] = 0.f;
    }
}

__global__ __launch_bounds__(256)
void softproj_kernel(const float* __restrict__ pc, const float* __restrict__ query,
                     const float* __restrict__ bp,
                     const float* __restrict__ temp, float* __restrict__ out)
{
    __shared__ float spx[MPTS], spy[MPTS], spz[MPTS];
    const int b = blockIdx.x;
    const float* p = pc + (size_t)b * 3 * MPTS;
    for (int i = threadIdx.x; i < MPTS; i += 256) {
        spx[i] = p[i]; spy[i] = p[MPTS + i]; spz[i] = p[2 * MPTS + i];
    }
    __syncthreads();

    const float t = temp[0];
    const float invsig = 1.f / (fmaxf(t * t, 1e-4f) + 1e-8f);
    const float bp0 = bp[0], bp1 = bp[1], bp2 = bp[2];
    const int warp = threadIdx.x >> 5, lane = threadIdx.x & 31;
    const int qbase = blockIdx.y * 64;

    for (int qq = 0; qq < 8; ++qq) {
        const int n = qbase + warp * 8 + qq;
        const float qx = query[((size_t)b * 3) * NQ + n] + bp0;
        const float qy = query[((size_t)b * 3 + 1) * NQ + n] + bp1;
        const float qz = query[((size_t)b * 3 + 2) * NQ + n] + bp2;

        float d[KNN]; int idx[KNN];
#pragma unroll
        for (int i = 0; i < KNN; i++) { d[i] = 1e30f; idx[i] = 0; }
        for (int m = lane; m < MPTS; m += 32) {
            float dx = spx[m] - qx, dy = spy[m] - qy, dz = spz[m] - qz;
            float dd = fmaf(dx, dx, fmaf(dy, dy, dz * dz));
            if (dd < d[KNN - 1]) {
                d[KNN - 1] = dd; idx[KNN - 1] = m;
#pragma unroll
                for (int j = KNN - 1; j > 0; --j)
                    if (d[j] < d[j - 1]) {
                        float td = d[j]; d[j] = d[j - 1]; d[j - 1] = td;
                        int ti = idx[j]; idx[j] = idx[j - 1]; idx[j - 1] = ti;
                    }
            }
        }
        float wsum = 0.f, ox = 0.f, oy = 0.f, oz = 0.f, dmin = 0.f;
#pragma unroll
        for (int k = 0; k < KNN; k++) {
            float cd = d[0]; int ci = idx[0];
#pragma unroll
            for (int off = 16; off; off >>= 1) {
                float od = __shfl_xor_sync(~0u, cd, off);
                int   oi = __shfl_xor_sync(~0u, ci, off);
                if (od < cd || (od == cd && oi < ci)) { cd = od; ci = oi; }
            }
            if (k == 0) dmin = cd;
            float w = __expf(-(cd - dmin) * invsig);
            wsum += w;
            ox = fmaf(w, spx[ci], ox); oy = fmaf(w, spy[ci], oy); oz = fmaf(w, spz[ci], oz);
            bool iwin = (d[0] == cd && idx[0] == ci);
            unsigned bal = __ballot_sync(~0u, iwin);
            if (lane == (__ffs(bal) - 1)) {
#pragma unroll
                for (int j = 0; j < KNN - 1; j++) { d[j] = d[j + 1]; idx[j] = idx[j + 1]; }
                d[KNN - 1] = 1e30f; idx[KNN - 1] = 0;
            }
        }
        if (lane == 0) {
            float inv = 1.f / wsum;
            out[((size_t)b * 3) * NQ + n] = ox * inv;
            out[((size_t)b * 3 + 1) * NQ + n] = oy * inv;
            out[((size_t)b * 3 + 2) * NQ + n] = oz * inv;
        }
    }
}

// ---------------------------------------------------------------------------
extern "C" void kernel_launch(void* const* d_in, const int* in_sizes, int n_in,
                              void* d_out, int out_size)
{
    const float* x     = (const float*)d_in[0];
    const float* pc    = (const float*)d_in[1];
    const float* Wqk   = (const float*)d_in[2];
    const float* Wv    = (const float*)d_in[3];
    const float* bv    = (const float*)d_in[4];
    const float* Wt    = (const float*)d_in[5];
    const float* bt    = (const float*)d_in[6];
    const float* gamma = (const float*)d_in[7];
    const float* beta  = (const float*)d_in[8];
    const float* Wp    = (const float*)d_in[9];
    const float* bp    = (const float*)d_in[10];
    const float* temp  = (const float*)d_in[11];
    float* out = (float*)d_out;

    float *Yv, *energy, *pm, *ps, *rmx, *rin, *query;
    u16 *xTh, *xTl, *Wqkh, *Wqkl, *Wvh, *Wvl, *Wth, *Wtl;
    u16 *Yqkth, *Yqktl, *dbufTh, *dbufTl;
    cudaGetSymbolAddress((void**)&xTh,   g_xTh);
    cudaGetSymbolAddress((void**)&xTl,   g_xTl);
    cudaGetSymbolAddress((void**)&Wqkh,  g_Wqkh);
    cudaGetSymbolAddress((void**)&Wqkl,  g_Wqkl);
    cudaGetSymbolAddress((void**)&Wvh,   g_Wvh);
    cudaGetSymbolAddress((void**)&Wvl,   g_Wvl);
    cudaGetSymbolAddress((void**)&Wth,   g_Wth);
    cudaGetSymbolAddress((void**)&Wtl,   g_Wtl);
    cudaGetSymbolAddress((void**)&Yqkth, g_Yqkth);
    cudaGetSymbolAddress((void**)&Yqktl, g_Yqktl);
    cudaGetSymbolAddress((void**)&Yv,    g_Yv);
    cudaGetSymbolAddress((void**)&energy,g_energy);
    cudaGetSymbolAddress((void**)&pm,    g_pm);
    cudaGetSymbolAddress((void**)&ps,    g_ps);
    cudaGetSymbolAddress((void**)&rmx,   g_rmax);
    cudaGetSymbolAddress((void**)&rin,   g_rinv);
    cudaGetSymbolAddress((void**)&dbufTh,g_dbufTh);
    cudaGetSymbolAddress((void**)&dbufTl,g_dbufTl);
    cudaGetSymbolAddress((void**)&query, g_query);

    const size_t CHNQ = (size_t)CH * NQ;
    const size_t NQNQ = (size_t)NQ * NQ;
    const size_t NQCH = (size_t)NQ * CH;

    cudaFuncSetAttribute(mma3bf<4, false>, cudaFuncAttributeMaxDynamicSharedMemorySize, 98304);
    cudaFuncSetAttribute(mma3bf<5, false>, cudaFuncAttributeMaxDynamicSharedMemorySize, 98304);
    cudaFuncSetAttribute(mma3bf<0, true >, cudaFuncAttributeMaxDynamicSharedMemorySize, 98304);
    cudaFuncSetAttribute(mma3bf<6, false>, cudaFuncAttributeMaxDynamicSharedMemorySize, 98304);
    cudaFuncSetAttribute(mma_xr, cudaFuncAttributeMaxDynamicSharedMemorySize, 81920);

    dim3 blk(256);
    transpose_x<<<dim3(NQ / 32, CH / 32, BATCH), blk>>>(x, xTh, xTl);
    split_w3z<<<960, 256>>>(Wqk, Wqkh, Wqkl, Wv, Wvh, Wvl, Wt, Wth, Wtl, query);
    mma3bf<4, false><<<dim3(16, 2, 8), blk, 98304>>>(
        xTh, xTl, NQCH, CH, Wqkh, Wqkl, 0, CH,
        nullptr, Yqkth, Yqktl, NQCH, CH, nullptr, nullptr, nullptr, nullptr, nullptr, nullptr);
    mma3bf<5, false><<<dim3(2, 16, 8), blk, 98304>>>(
        Wvh, Wvl, 0, CH, xTh, xTl, NQCH, CH,
        Yv, nullptr, nullptr, CHNQ, NQ, bv, nullptr, nullptr, nullptr, nullptr, nullptr);
    mma3bf<0, true><<<dim3(136, 1, 8), blk, 98304>>>(
        Yqkth, Yqktl, NQCH, CH, Yqkth, Yqktl, NQCH, CH,
        energy, nullptr, nullptr, NQNQ, NQ, nullptr, nullptr, nullptr, nullptr, pm, ps);
    stat_combine<<<BATCH * NQ / 256, 256>>>(pm, ps, rmx, rin);
    mma_xr<<<dim3(32, 1, 8), blk, 81920>>>(energy, Yv, rmx, rin, xTh, xTl, dbufTh, dbufTl);
    mma3bf<6, false><<<dim3(2, 16, 8), blk, 98304>>>(
        Wth, Wtl, 0, CH, dbufTh, dbufTl, NQCH, CH,
        nullptr, nullptr, nullptr, CHNQ, NQ, bt, gamma, beta, x, (float*)Wp, query);
    softproj_kernel<<<dim3(BATCH, NQ / 64), 256>>>(pc, query, bp, temp, out);
}